// round 15
// baseline (speedup 1.0000x reference)
#include <cuda_runtime.h>
#include <cuda_fp16.h>

#define CB 4
#define CS 2048
#define CD 1024
#define CH 16
#define MTOK (CB*CS)

#define GM MTOK
#define GN CD
#define GK CD

/* half scratch (device globals: allocation-free, graph-capturable) */
__device__ __half g_hQ [MTOK * CD];
__device__ __half g_hKV[MTOK * CD];
__device__ __half g_hWq[CD * CD];
__device__ __half g_hWk[CD * CD];
__device__ __half g_hWv[CD * CD];
__device__ __half g_hWo[CD * CD];
__device__ __half g_hq [MTOK * CD];
__device__ __half g_hk [MTOK * CD];
__device__ __half g_hv [MTOK * CD];
__device__ __half g_hctx[MTOK * CD];

/* ---------------- helpers ---------------- */
__device__ __forceinline__ unsigned sptr(const void* p) {
    return (unsigned)__cvta_generic_to_shared(p);
}
__device__ __forceinline__ void ldsm4(unsigned& r0, unsigned& r1, unsigned& r2,
                                      unsigned& r3, unsigned addr) {
    asm volatile("ldmatrix.sync.aligned.m8n8.x4.shared.b16 {%0,%1,%2,%3}, [%4];"
                 : "=r"(r0), "=r"(r1), "=r"(r2), "=r"(r3) : "r"(addr));
}
__device__ __forceinline__ void ldsm4t(unsigned& r0, unsigned& r1, unsigned& r2,
                                       unsigned& r3, unsigned addr) {
    asm volatile("ldmatrix.sync.aligned.m8n8.x4.trans.shared.b16 {%0,%1,%2,%3}, [%4];"
                 : "=r"(r0), "=r"(r1), "=r"(r2), "=r"(r3) : "r"(addr));
}
__device__ __forceinline__ void mma16816(float* c, const unsigned* a,
                                         unsigned b0, unsigned b1) {
    asm volatile(
        "mma.sync.aligned.m16n8k16.row.col.f32.f16.f16.f32 "
        "{%0,%1,%2,%3}, {%4,%5,%6,%7}, {%8,%9}, {%0,%1,%2,%3};"
        : "+f"(c[0]), "+f"(c[1]), "+f"(c[2]), "+f"(c[3])
        : "r"(a[0]), "r"(a[1]), "r"(a[2]), "r"(a[3]), "r"(b0), "r"(b1));
}
__device__ __forceinline__ void cpa16(unsigned dst, const void* src) {
    asm volatile("cp.async.cg.shared.global [%0], [%1], 16;" :: "r"(dst), "l"(src));
}
__device__ __forceinline__ float ex2(float x) {
    float y; asm("ex2.approx.ftz.f32 %0, %1;" : "=f"(y) : "f"(x)); return y;
}
__device__ __forceinline__ unsigned packh2(float lo, float hi) {
    __half2 h = __float22half2_rn(make_float2(lo, hi));
    return *reinterpret_cast<unsigned*>(&h);
}

/* ---------------- fp32 -> fp16 converts (grid-stride, ILP) -------- */
__global__ void f2h2_kernel(const float4* __restrict__ x0, const float4* __restrict__ x1,
                            uint2* __restrict__ y0, uint2* __restrict__ y1, int n4)
{
    const float4* x = (blockIdx.y == 0) ? x0 : x1;
    uint2* y = (blockIdx.y == 0) ? y0 : y1;
    int stride = gridDim.x * blockDim.x;
    for (int i = blockIdx.x * blockDim.x + threadIdx.x; i < n4; i += stride) {
        float4 f = x[i];
        uint2 u;
        u.x = packh2(f.x, f.y);
        u.y = packh2(f.z, f.w);
        y[i] = u;
    }
}

__global__ void f2h4_kernel(const float4* __restrict__ x0, const float4* __restrict__ x1,
                            const float4* __restrict__ x2, const float4* __restrict__ x3,
                            uint2* __restrict__ y0, uint2* __restrict__ y1,
                            uint2* __restrict__ y2, uint2* __restrict__ y3, int n4)
{
    const float4* x = (blockIdx.y == 0) ? x0 : (blockIdx.y == 1) ? x1
                    : (blockIdx.y == 2) ? x2 : x3;
    uint2* y = (blockIdx.y == 0) ? y0 : (blockIdx.y == 1) ? y1
             : (blockIdx.y == 2) ? y2 : y3;
    int stride = gridDim.x * blockDim.x;
    for (int i = blockIdx.x * blockDim.x + threadIdx.x; i < n4; i += stride) {
        float4 f = x[i];
        uint2 u;
        u.x = packh2(f.x, f.y);
        u.y = packh2(f.z, f.w);
        y[i] = u;
    }
}

/* ------------------------------------------------------------------ */
/* fp16 tensor-core GEMM: C[M,N] = A[M,K] @ B[K,N] + bias             */
/* 128x128x64 tile, 8 warps (warp 32x64), mma.m16n8k16, cp.async x3.  */
/* BK=64: half the barriers of BK=32, 4x-longer MMA stretch per tile. */
/* ------------------------------------------------------------------ */
#define GAH 72    /* As stride (halfs): 144B = 9x16B, odd -> conflict-free */
#define GBH 136   /* Bs stride (halfs): 272B = 17x16B, conflict-free      */
#define STG_A (128 * GAH)   /* halfs per A stage */
#define STG_B (64 * GBH)    /* halfs per B stage */
#define GEMM_SMEM ((3 * STG_A + 3 * STG_B) * 2)   /* 107520 bytes */

template<bool HALF_OUT>
__global__ __launch_bounds__(256)
void gemm_h_kernel(const __half* __restrict__ A, const __half* __restrict__ B,
                   const float* __restrict__ bias,
                   float* __restrict__ Cf, __half* __restrict__ Ch)
{
    extern __shared__ __half gsm[];
    __half* AsBase = gsm;                 /* [3][128*GAH] */
    __half* BsBase = gsm + 3 * STG_A;     /* [3][64*GBH]  */

    const int tid  = threadIdx.x;
    const int lane = tid & 31;
    const int gr   = lane >> 2;
    const int tg   = lane & 3;
    const int warp = tid >> 5;
    const int wm   = (warp & 3) * 32;
    const int wn   = (warp >> 2) * 64;
    const int bm   = blockIdx.y * 128;
    const int bn   = blockIdx.x * 128;

    /* cp.async copy indices (per 64-deep K stage) */
    const int arow = tid >> 1;            /* 0..127 */
    const int acol = (tid & 1) * 32;      /* halfs: 0 or 32 */
    const int brow = tid >> 2;            /* 0..63  */
    const int bcol = (tid & 3) * 32;      /* halfs: 0,32,64,96 */

    const __half* Ag = A + (size_t)(bm + arow) * GK + acol;
    const __half* Bg = B + (size_t)brow * GN + bn + bcol;

    float acc[2][8][4];
#pragma unroll
    for (int mt = 0; mt < 2; mt++)
#pragma unroll
        for (int nt = 0; nt < 8; nt++)
#pragma unroll
            for (int i = 0; i < 4; i++) acc[mt][nt][i] = 0.f;

    const int l15 = lane & 15;
    const int lk8 = (lane & 16) >> 1;     /* 0 or 8 */

#define G_ISSUE(st, k0) do {                                              \
        unsigned da = sptr(AsBase + (st) * STG_A + arow * GAH + acol);    \
        _Pragma("unroll")                                                 \
        for (int j = 0; j < 4; j++)                                       \
            cpa16(da + j * 16, Ag + (k0) + j * 8);                        \
        unsigned db = sptr(BsBase + (st) * STG_B + brow * GBH + bcol);    \
        _Pragma("unroll")                                                 \
        for (int j = 0; j < 4; j++)                                       \
            cpa16(db + j * 16, Bg + (size_t)(k0) * GN + j * 8);           \
        asm volatile("cp.async.commit_group;");                           \
    } while (0)

    G_ISSUE(0, 0);
    G_ISSUE(1, 64);

    int st = 0;
    for (int kt = 0; kt < 16; kt++) {
        if (kt < 15) asm volatile("cp.async.wait_group 1;");
        else         asm volatile("cp.async.wait_group 0;");
        __syncthreads();
        if (kt < 14) { int ns = kt + 2 - ((kt + 2) / 3) * 3; G_ISSUE(ns, (kt + 2) * 64); }

        const __half* as = AsBase + st * STG_A;
        const __half* bs = BsBase + st * STG_B;
#pragma unroll
        for (int ks = 0; ks < 64; ks += 16) {
            unsigned af[2][4];
            ldsm4(af[0][0], af[0][1], af[0][2], af[0][3],
                  sptr(&as[(wm + l15) * GAH + ks + lk8]));
            ldsm4(af[1][0], af[1][1], af[1][2], af[1][3],
                  sptr(&as[(wm + 16 + l15) * GAH + ks + lk8]));
#pragma unroll
            for (int nt2 = 0; nt2 < 4; nt2++) {
                unsigned b0, b1, b2, b3;
                ldsm4t(b0, b1, b2, b3,
                       sptr(&bs[(ks + (lane & 7) + (lane & 8)) * GBH
                                + wn + nt2 * 16 + lk8]));
                mma16816(acc[0][2 * nt2],     af[0], b0, b1);
                mma16816(acc[1][2 * nt2],     af[1], b0, b1);
                mma16816(acc[0][2 * nt2 + 1], af[0], b2, b3);
                mma16816(acc[1][2 * nt2 + 1], af[1], b2, b3);
            }
        }
        st++; if (st == 3) st = 0;
    }
#undef G_ISSUE

    /* epilogue: bias + store */
#pragma unroll
    for (int mt = 0; mt < 2; mt++) {
#pragma unroll
        for (int nt = 0; nt < 8; nt++) {
            int row = bm + wm + mt * 16 + gr;
            int col = bn + wn + nt * 8 + tg * 2;
            float2 bb = *(const float2*)(bias + col);
            float c0 = acc[mt][nt][0] + bb.x, c1 = acc[mt][nt][1] + bb.y;
            float c2 = acc[mt][nt][2] + bb.x, c3 = acc[mt][nt][3] + bb.y;
            if (HALF_OUT) {
                *reinterpret_cast<unsigned*>(Ch + (size_t)row * GN + col) = packh2(c0, c1);
                *reinterpret_cast<unsigned*>(Ch + (size_t)(row + 8) * GN + col) = packh2(c2, c3);
            } else {
                *(float2*)(Cf + (size_t)row * GN + col) = make_float2(c0, c1);
                *(float2*)(Cf + (size_t)(row + 8) * GN + col) = make_float2(c2, c3);
            }
        }
    }
}

/* ------------------------------------------------------------------ */
/* FA2-style fp16 tensor-core flash attention (causal).               */
/* CTA = 128 q-rows x (b,h); warp owns 16 rows x full 64-col S.       */
/* K/V double-buffered via cp.async; 1 barrier per k-tile.            */
/* ------------------------------------------------------------------ */
#define FQH 72   /* smem stride (halfs): 144B; 9r%8 distinct quads */
#define FLASH_SMEM ((128*FQH + 4*64*FQH) * 2)   /* 55296 bytes */

__global__ __launch_bounds__(256, 2)
void flash_h_kernel(const __half* __restrict__ q, const __half* __restrict__ k,
                    const __half* __restrict__ v, __half* __restrict__ ctx)
{
    extern __shared__ __half fsm[];
    __half* Qs  = fsm;                       /* [128][FQH] */
    __half* KsB = fsm + 128 * FQH;           /* [2][64][FQH] */
    __half* VsB = fsm + 128 * FQH + 2 * 64 * FQH;

    const int tid  = threadIdx.x;
    const int lane = tid & 31;
    const int gr   = lane >> 2;
    const int tg   = lane & 3;
    const int warp = tid >> 5;
    const int l15  = lane & 15;
    const int lk8  = (lane & 16) >> 1;   /* 0 or 8 */

    const int qt = 15 - blockIdx.x;      /* heavy tiles first */
    const int bh = blockIdx.y;
    const int b  = bh >> 4;
    const int h  = bh & 15;
    const int qbase = qt * 128;

    const __half* qp = q + ((size_t)b * CS + qbase) * CD + h * 64;
    const __half* kp = k + ((size_t)b * CS) * CD + h * 64;
    const __half* vp = v + ((size_t)b * CS) * CD + h * 64;

    const int srow = tid >> 2;           /* 0..63 */
    const int scol = (tid & 3) * 16;     /* 0,16,32,48 */

#define F_ISSUE(kt, buf) do {                                                \
        const __half* ksrc = kp + (size_t)((kt) * 64 + srow) * CD + scol;    \
        unsigned dk = sptr(KsB + (buf) * 64 * FQH + srow * FQH + scol);      \
        cpa16(dk,      ksrc);                                                \
        cpa16(dk + 16, ksrc + 8);                                            \
        const __half* vsrc = vp + (size_t)((kt) * 64 + srow) * CD + scol;    \
        unsigned dv = sptr(VsB + (buf) * 64 * FQH + srow * FQH + scol);      \
        cpa16(dv,      vsrc);                                                \
        cpa16(dv + 16, vsrc + 8);                                            \
        asm volatile("cp.async.commit_group;");                              \
    } while (0)

    F_ISSUE(0, 0);
    {
        int r  = tid >> 1;
        int c0 = (tid & 1) * 32;
        const __half* src = qp + (size_t)r * CD + c0;
#pragma unroll
        for (int j = 0; j < 4; j++)
            *(uint4*)&Qs[r * FQH + c0 + j * 8] = *(const uint4*)(src + j * 8);
    }
    __syncthreads();

    unsigned qf[4][4];
#pragma unroll
    for (int ks = 0; ks < 4; ks++)
        ldsm4(qf[ks][0], qf[ks][1], qf[ks][2], qf[ks][3],
              sptr(&Qs[(warp * 16 + l15) * FQH + ks * 16 + lk8]));

    float o[8][4];
#pragma unroll
    for (int dt = 0; dt < 8; dt++)
#pragma unroll
        for (int i = 0; i < 4; i++) o[dt][i] = 0.f;
    float mrow0 = -1e30f, mrow1 = -1e30f;
    float lrow0 = 0.f,    lrow1 = 0.f;

    const int qrow0 = qbase + warp * 16;
    const int nkt = (qbase >> 6) + 2;
    const float SC = 0.18033688f;   /* (1/8) * log2(e) */

    int buf = 0;
    for (int kt = 0; kt < nkt; kt++) {
        asm volatile("cp.async.wait_group 0;");
        __syncthreads();   /* K/V[buf] ready; all warps done with buf^1 */
        if (kt + 1 < nkt) F_ISSUE(kt + 1, buf ^ 1);

        if (kt * 64 <= qrow0 + 15) {
            const __half* Ks = KsB + buf * 64 * FQH;
            const __half* Vs = VsB + buf * 64 * FQH;

            float s[8][4];
#pragma unroll
            for (int nt = 0; nt < 8; nt++)
#pragma unroll
                for (int i = 0; i < 4; i++) s[nt][i] = 0.f;
#pragma unroll
            for (int ks = 0; ks < 4; ks++) {
#pragma unroll
                for (int nt2 = 0; nt2 < 4; nt2++) {
                    unsigned b0, b1, b2, b3;
                    ldsm4(b0, b1, b2, b3,
                          sptr(&Ks[(nt2 * 16 + (lane & 7) + lk8) * FQH
                                   + ks * 16 + (lane & 8)]));
                    mma16816(s[2 * nt2],     qf[ks], b0, b1);
                    mma16816(s[2 * nt2 + 1], qf[ks], b2, b3);
                }
            }

            const bool dg = (kt * 64 + 63 > qrow0);
            const int r0r = qrow0 + gr, r1r = qrow0 + gr + 8;
#pragma unroll
            for (int nt = 0; nt < 8; nt++) {
                int col = kt * 64 + nt * 8 + 2 * tg;
                if (dg) {
                    s[nt][0] = (col     > r0r) ? -1e30f : s[nt][0] * SC;
                    s[nt][1] = (col + 1 > r0r) ? -1e30f : s[nt][1] * SC;
                    s[nt][2] = (col     > r1r) ? -1e30f : s[nt][2] * SC;
                    s[nt][3] = (col + 1 > r1r) ? -1e30f : s[nt][3] * SC;
                } else {
                    s[nt][0] *= SC; s[nt][1] *= SC;
                    s[nt][2] *= SC; s[nt][3] *= SC;
                }
            }

            float mx0 = -1e30f, mx1 = -1e30f;
#pragma unroll
            for (int nt = 0; nt < 8; nt++) {
                mx0 = fmaxf(mx0, fmaxf(s[nt][0], s[nt][1]));
                mx1 = fmaxf(mx1, fmaxf(s[nt][2], s[nt][3]));
            }
            mx0 = fmaxf(mx0, __shfl_xor_sync(0xffffffffu, mx0, 1));
            mx0 = fmaxf(mx0, __shfl_xor_sync(0xffffffffu, mx0, 2));
            mx1 = fmaxf(mx1, __shfl_xor_sync(0xffffffffu, mx1, 1));
            mx1 = fmaxf(mx1, __shfl_xor_sync(0xffffffffu, mx1, 2));
            float mn0 = fmaxf(mrow0, mx0), mn1 = fmaxf(mrow1, mx1);
            float rs0 = ex2(mrow0 - mn0), rs1 = ex2(mrow1 - mn1);
            mrow0 = mn0; mrow1 = mn1;
            float ls0 = 0.f, ls1 = 0.f;
#pragma unroll
            for (int nt = 0; nt < 8; nt++) {
                s[nt][0] = ex2(s[nt][0] - mn0); ls0 += s[nt][0];
                s[nt][1] = ex2(s[nt][1] - mn0); ls0 += s[nt][1];
                s[nt][2] = ex2(s[nt][2] - mn1); ls1 += s[nt][2];
                s[nt][3] = ex2(s[nt][3] - mn1); ls1 += s[nt][3];
            }
            ls0 += __shfl_xor_sync(0xffffffffu, ls0, 1);
            ls0 += __shfl_xor_sync(0xffffffffu, ls0, 2);
            ls1 += __shfl_xor_sync(0xffffffffu, ls1, 1);
            ls1 += __shfl_xor_sync(0xffffffffu, ls1, 2);
            lrow0 = lrow0 * rs0 + ls0;
            lrow1 = lrow1 * rs1 + ls1;

#pragma unroll
            for (int dt = 0; dt < 8; dt++) {
                o[dt][0] *= rs0; o[dt][1] *= rs0;
                o[dt][2] *= rs1; o[dt][3] *= rs1;
            }

            unsigned pf[4][4];
#pragma unroll
            for (int ks = 0; ks < 4; ks++) {
                pf[ks][0] = packh2(s[2 * ks][0],     s[2 * ks][1]);
                pf[ks][1] = packh2(s[2 * ks][2],     s[2 * ks][3]);
                pf[ks][2] = packh2(s[2 * ks + 1][0], s[2 * ks + 1][1]);
                pf[ks][3] = packh2(s[2 * ks + 1][2], s[2 * ks + 1][3]);
            }

#pragma unroll
            for (int ks = 0; ks < 4; ks++) {
#pragma unroll
                for (int dt2 = 0; dt2 < 4; dt2++) {
                    unsigned b0, b1, b2, b3;
                    ldsm4t(b0, b1, b2, b3,
                           sptr(&Vs[(ks * 16 + (lane & 7) + (lane & 8)) * FQH
                                    + dt2 * 16 + lk8]));
                    mma16816(o[2 * dt2],     pf[ks], b0, b1);
                    mma16816(o[2 * dt2 + 1], pf[ks], b2, b3);
                }
            }
        }
        buf ^= 1;
    }
#undef F_ISSUE

    float inv0 = 1.f / lrow0, inv1 = 1.f / lrow1;
    __half* op = ctx + ((size_t)b * CS + qrow0) * CD + h * 64;
#pragma unroll
    for (int dt = 0; dt < 8; dt++) {
        int col = dt * 8 + 2 * tg;
        *reinterpret_cast<unsigned*>(op + (size_t)gr * CD + col) =
            packh2(o[dt][0] * inv0, o[dt][1] * inv0);
        *reinterpret_cast<unsigned*>(op + (size_t)(gr + 8) * CD + col) =
            packh2(o[dt][2] * inv1, o[dt][3] * inv1);
    }
}

/* ------------------------------------------------------------------ */
extern "C" void kernel_launch(void* const* d_in, const int* in_sizes, int n_in,
                              void* d_out, int out_size)
{
    const float* Q  = (const float*)d_in[0];
    const float* KV = (const float*)d_in[1];
    /* d_in[2] = mask — causal, applied analytically */
    const float* Wq = (const float*)d_in[3];
    const float* bq = (const float*)d_in[4];
    const float* Wk = (const float*)d_in[5];
    const float* bk = (const float*)d_in[6];
    const float* Wv = (const float*)d_in[7];
    const float* bv = (const float*)d_in[8];
    const float* Wo = (const float*)d_in[9];
    const float* bo = (const float*)d_in[10];
    float* out = (float*)d_out;

    __half *hQ, *hKV, *hWq, *hWk, *hWv, *hWo, *hq, *hk, *hv, *hctx;
    cudaGetSymbolAddress((void**)&hQ,   g_hQ);
    cudaGetSymbolAddress((void**)&hKV,  g_hKV);
    cudaGetSymbolAddress((void**)&hWq,  g_hWq);
    cudaGetSymbolAddress((void**)&hWk,  g_hWk);
    cudaGetSymbolAddress((void**)&hWv,  g_hWv);
    cudaGetSymbolAddress((void**)&hWo,  g_hWo);
    cudaGetSymbolAddress((void**)&hq,   g_hq);
    cudaGetSymbolAddress((void**)&hk,   g_hk);
    cudaGetSymbolAddress((void**)&hv,   g_hv);
    cudaGetSymbolAddress((void**)&hctx, g_hctx);

    static bool attr_done = false;
    if (!attr_done) {
        cudaFuncSetAttribute(gemm_h_kernel<true>,
                             cudaFuncAttributeMaxDynamicSharedMemorySize, GEMM_SMEM);
        cudaFuncSetAttribute(gemm_h_kernel<false>,
                             cudaFuncAttributeMaxDynamicSharedMemorySize, GEMM_SMEM);
        cudaFuncSetAttribute(flash_h_kernel,
                             cudaFuncAttributeMaxDynamicSharedMemorySize, FLASH_SMEM);
        attr_done = true;
    }

    const int NTOK4 = MTOK * CD / 4;   /* 2M float4 */
    const int NW4   = CD * CD / 4;     /* 256K float4 */
    f2h2_kernel<<<dim3(1184, 2), 256>>>((const float4*)Q, (const float4*)KV,
                                        (uint2*)hQ, (uint2*)hKV, NTOK4);
    f2h4_kernel<<<dim3(296, 4), 256>>>(
        (const float4*)Wq, (const float4*)Wk, (const float4*)Wv, (const float4*)Wo,
        (uint2*)hWq, (uint2*)hWk, (uint2*)hWv, (uint2*)hWo, NW4);

    dim3 gg(GN / 128, GM / 128);   /* (8, 64) */
    gemm_h_kernel<true><<<gg, 256, GEMM_SMEM>>>(hQ,  hWq, bq, nullptr, hq);
    gemm_h_kernel<true><<<gg, 256, GEMM_SMEM>>>(hKV, hWk, bk, nullptr, hk);
    gemm_h_kernel<true><<<gg, 256, GEMM_SMEM>>>(hKV, hWv, bv, nullptr, hv);

    dim3 gf(16, CB * CH);          /* (16, 64) */
    flash_h_kernel<<<gf, 256, FLASH_SMEM>>>(hq, hk, hv, hctx);

    gemm_h_kernel<false><<<gg, 256, GEMM_SMEM>>>(hctx, hWo, bo, out, nullptr);
}

// round 16
// speedup vs baseline: 1.7337x; 1.7337x over previous
#include <cuda_runtime.h>
#include <cuda_fp16.h>

#define CB 4
#define CS 2048
#define CD 1024
#define CH 16
#define MTOK (CB*CS)

#define GM MTOK
#define GN CD
#define GK CD

/* half scratch (device globals: allocation-free, graph-capturable) */
__device__ __half g_hQ [MTOK * CD];
__device__ __half g_hKV[MTOK * CD];
__device__ __half g_hWq[CD * CD];
__device__ __half g_hWk[CD * CD];
__device__ __half g_hWv[CD * CD];
__device__ __half g_hWo[CD * CD];
__device__ __half g_hq [MTOK * CD];
__device__ __half g_hk [MTOK * CD];
__device__ __half g_hv [MTOK * CD];
__device__ __half g_hctx[MTOK * CD];

/* ---------------- helpers ---------------- */
__device__ __forceinline__ unsigned sptr(const void* p) {
    return (unsigned)__cvta_generic_to_shared(p);
}
__device__ __forceinline__ void ldsm4(unsigned& r0, unsigned& r1, unsigned& r2,
                                      unsigned& r3, unsigned addr) {
    asm volatile("ldmatrix.sync.aligned.m8n8.x4.shared.b16 {%0,%1,%2,%3}, [%4];"
                 : "=r"(r0), "=r"(r1), "=r"(r2), "=r"(r3) : "r"(addr));
}
__device__ __forceinline__ void ldsm4t(unsigned& r0, unsigned& r1, unsigned& r2,
                                       unsigned& r3, unsigned addr) {
    asm volatile("ldmatrix.sync.aligned.m8n8.x4.trans.shared.b16 {%0,%1,%2,%3}, [%4];"
                 : "=r"(r0), "=r"(r1), "=r"(r2), "=r"(r3) : "r"(addr));
}
__device__ __forceinline__ void mma16816(float* c, const unsigned* a,
                                         unsigned b0, unsigned b1) {
    asm volatile(
        "mma.sync.aligned.m16n8k16.row.col.f32.f16.f16.f32 "
        "{%0,%1,%2,%3}, {%4,%5,%6,%7}, {%8,%9}, {%0,%1,%2,%3};"
        : "+f"(c[0]), "+f"(c[1]), "+f"(c[2]), "+f"(c[3])
        : "r"(a[0]), "r"(a[1]), "r"(a[2]), "r"(a[3]), "r"(b0), "r"(b1));
}
__device__ __forceinline__ void cpa16(unsigned dst, const void* src) {
    asm volatile("cp.async.cg.shared.global [%0], [%1], 16;" :: "r"(dst), "l"(src));
}
__device__ __forceinline__ float ex2(float x) {
    float y; asm("ex2.approx.ftz.f32 %0, %1;" : "=f"(y) : "f"(x)); return y;
}
__device__ __forceinline__ unsigned packh2(float lo, float hi) {
    __half2 h = __float22half2_rn(make_float2(lo, hi));
    return *reinterpret_cast<unsigned*>(&h);
}

/* ---------------- fp32 -> fp16 converts (grid-stride, ILP) -------- */
__global__ void f2h2_kernel(const float4* __restrict__ x0, const float4* __restrict__ x1,
                            uint2* __restrict__ y0, uint2* __restrict__ y1, int n4)
{
    const float4* x = (blockIdx.y == 0) ? x0 : x1;
    uint2* y = (blockIdx.y == 0) ? y0 : y1;
    int stride = gridDim.x * blockDim.x;
    for (int i = blockIdx.x * blockDim.x + threadIdx.x; i < n4; i += stride) {
        float4 f = x[i];
        uint2 u;
        u.x = packh2(f.x, f.y);
        u.y = packh2(f.z, f.w);
        y[i] = u;
    }
}

__global__ void f2h4_kernel(const float4* __restrict__ x0, const float4* __restrict__ x1,
                            const float4* __restrict__ x2, const float4* __restrict__ x3,
                            uint2* __restrict__ y0, uint2* __restrict__ y1,
                            uint2* __restrict__ y2, uint2* __restrict__ y3, int n4)
{
    const float4* x = (blockIdx.y == 0) ? x0 : (blockIdx.y == 1) ? x1
                    : (blockIdx.y == 2) ? x2 : x3;
    uint2* y = (blockIdx.y == 0) ? y0 : (blockIdx.y == 1) ? y1
             : (blockIdx.y == 2) ? y2 : y3;
    int stride = gridDim.x * blockDim.x;
    for (int i = blockIdx.x * blockDim.x + threadIdx.x; i < n4; i += stride) {
        float4 f = x[i];
        uint2 u;
        u.x = packh2(f.x, f.y);
        u.y = packh2(f.z, f.w);
        y[i] = u;
    }
}

/* ------------------------------------------------------------------ */
/* fp16 tensor-core GEMM body: C[M,N] = A[M,K] @ B[K,N] + bias        */
/* R12-proven config: 128x128x32 tile, 8 warps, mma.m16n8k16,         */
/* 3-stage cp.async, natural regs (2 CTAs/SM).                        */
/* ------------------------------------------------------------------ */
#define GAH 40    /* As stride (halfs): 80B;  5r%8  distinct quads    */
#define GBH 136   /* Bs stride (halfs): 272B; 17r%8 distinct quads    */
#define GEMM_SMEM ((3*128*GAH + 3*32*GBH) * 2)   /* 56832 bytes */

template<bool HALF_OUT>
__device__ __forceinline__
void gemm_body(const __half* __restrict__ A, const __half* __restrict__ B,
               const float* __restrict__ bias,
               float* __restrict__ Cf, __half* __restrict__ Ch,
               __half* gsm)
{
    __half* AsBase = gsm;                    /* [3][128*GAH] */
    __half* BsBase = gsm + 3 * 128 * GAH;    /* [3][32*GBH]  */

    const int tid  = threadIdx.x;
    const int lane = tid & 31;
    const int gr   = lane >> 2;
    const int tg   = lane & 3;
    const int warp = tid >> 5;
    const int wm   = (warp & 3) * 32;
    const int wn   = (warp >> 2) * 64;
    const int bm   = blockIdx.y * 128;
    const int bn   = blockIdx.x * 128;

    const int arow = tid >> 1;            /* 0..127 */
    const int acol = (tid & 1) * 16;      /* halfs  */
    const int brow = tid >> 3;            /* 0..31  */
    const int bcol = (tid & 7) * 16;      /* halfs  */

    const __half* Ag = A + (size_t)(bm + arow) * GK + acol;
    const __half* Bg = B + (size_t)brow * GN + bn + bcol;

    float acc[2][8][4];
#pragma unroll
    for (int mt = 0; mt < 2; mt++)
#pragma unroll
        for (int nt = 0; nt < 8; nt++)
#pragma unroll
            for (int i = 0; i < 4; i++) acc[mt][nt][i] = 0.f;

    const int l15 = lane & 15;
    const int lk8 = (lane & 16) >> 1;     /* 0 or 8 */

#define G_ISSUE(st, k0) do {                                              \
        unsigned da = sptr(AsBase + (st) * 128 * GAH + arow * GAH + acol);\
        cpa16(da,      Ag + (k0));                                        \
        cpa16(da + 16, Ag + (k0) + 8);                                    \
        unsigned db = sptr(BsBase + (st) * 32 * GBH + brow * GBH + bcol); \
        cpa16(db,      Bg + (size_t)(k0) * GN);                           \
        cpa16(db + 16, Bg + (size_t)(k0) * GN + 8);                       \
        asm volatile("cp.async.commit_group;");                           \
    } while (0)

    G_ISSUE(0, 0);
    G_ISSUE(1, 32);

    int st = 0;
    for (int kt = 0; kt < 32; kt++) {
        if (kt < 31) asm volatile("cp.async.wait_group 1;");
        else         asm volatile("cp.async.wait_group 0;");
        __syncthreads();
        if (kt < 30) { int ns = kt + 2 - ((kt + 2) / 3) * 3; G_ISSUE(ns, (kt + 2) * 32); }

        const __half* as = AsBase + st * 128 * GAH;
        const __half* bs = BsBase + st * 32 * GBH;
#pragma unroll
        for (int ks = 0; ks < 32; ks += 16) {
            unsigned af[2][4];
            ldsm4(af[0][0], af[0][1], af[0][2], af[0][3],
                  sptr(&as[(wm + l15) * GAH + ks + lk8]));
            ldsm4(af[1][0], af[1][1], af[1][2], af[1][3],
                  sptr(&as[(wm + 16 + l15) * GAH + ks + lk8]));
#pragma unroll
            for (int nt2 = 0; nt2 < 4; nt2++) {
                unsigned b0, b1, b2, b3;
                ldsm4t(b0, b1, b2, b3,
                       sptr(&bs[(ks + (lane & 7) + (lane & 8)) * GBH
                                + wn + nt2 * 16 + lk8]));
                mma16816(acc[0][2 * nt2],     af[0], b0, b1);
                mma16816(acc[1][2 * nt2],     af[1], b0, b1);
                mma16816(acc[0][2 * nt2 + 1], af[0], b2, b3);
                mma16816(acc[1][2 * nt2 + 1], af[1], b2, b3);
            }
        }
        st++; if (st == 3) st = 0;
    }
#undef G_ISSUE

    /* epilogue: bias + store */
#pragma unroll
    for (int mt = 0; mt < 2; mt++) {
#pragma unroll
        for (int nt = 0; nt < 8; nt++) {
            int row = bm + wm + mt * 16 + gr;
            int col = bn + wn + nt * 8 + tg * 2;
            float2 bb = *(const float2*)(bias + col);
            float c0 = acc[mt][nt][0] + bb.x, c1 = acc[mt][nt][1] + bb.y;
            float c2 = acc[mt][nt][2] + bb.x, c3 = acc[mt][nt][3] + bb.y;
            if (HALF_OUT) {
                *reinterpret_cast<unsigned*>(Ch + (size_t)row * GN + col) = packh2(c0, c1);
                *reinterpret_cast<unsigned*>(Ch + (size_t)(row + 8) * GN + col) = packh2(c2, c3);
            } else {
                *(float2*)(Cf + (size_t)row * GN + col) = make_float2(c0, c1);
                *(float2*)(Cf + (size_t)(row + 8) * GN + col) = make_float2(c2, c3);
            }
        }
    }
}

/* fused q/k/v projections: blockIdx.z selects {A, W, bias, out} */
__global__ __launch_bounds__(256)
void gemm_qkv_kernel(const __half* __restrict__ hQ, const __half* __restrict__ hKV,
                     const __half* __restrict__ Wq, const __half* __restrict__ Wk,
                     const __half* __restrict__ Wv,
                     const float* __restrict__ bq, const float* __restrict__ bk,
                     const float* __restrict__ bv,
                     __half* __restrict__ oq, __half* __restrict__ ok,
                     __half* __restrict__ ov)
{
    extern __shared__ __half gsm[];
    const int z = blockIdx.z;
    const __half* A = (z == 0) ? hQ : hKV;
    const __half* W = (z == 0) ? Wq : (z == 1) ? Wk : Wv;
    const float*  b = (z == 0) ? bq : (z == 1) ? bk : bv;
    __half*       C = (z == 0) ? oq : (z == 1) ? ok : ov;
    gemm_body<true>(A, W, b, nullptr, C, gsm);
}

/* output projection: fp32 out */
__global__ __launch_bounds__(256)
void gemm_wo_kernel(const __half* __restrict__ A, const __half* __restrict__ W,
                    const float* __restrict__ bias, float* __restrict__ C)
{
    extern __shared__ __half gsm[];
    gemm_body<false>(A, W, bias, C, nullptr, gsm);
}

/* ------------------------------------------------------------------ */
/* FA2-style fp16 tensor-core flash attention (causal).               */
/* CTA = 128 q-rows x (b,h); warp owns 16 rows x full 64-col S.       */
/* K/V double-buffered via cp.async; 1 barrier per k-tile.            */
/* ------------------------------------------------------------------ */
#define FQH 72   /* smem stride (halfs): 144B; 9r%8 distinct quads */
#define FLASH_SMEM ((128*FQH + 4*64*FQH) * 2)   /* 55296 bytes */

__global__ __launch_bounds__(256, 2)
void flash_h_kernel(const __half* __restrict__ q, const __half* __restrict__ k,
                    const __half* __restrict__ v, __half* __restrict__ ctx)
{
    extern __shared__ __half fsm[];
    __half* Qs  = fsm;                       /* [128][FQH] */
    __half* KsB = fsm + 128 * FQH;           /* [2][64][FQH] */
    __half* VsB = fsm + 128 * FQH + 2 * 64 * FQH;

    const int tid  = threadIdx.x;
    const int lane = tid & 31;
    const int gr   = lane >> 2;
    const int tg   = lane & 3;
    const int warp = tid >> 5;
    const int l15  = lane & 15;
    const int lk8  = (lane & 16) >> 1;   /* 0 or 8 */

    const int qt = 15 - blockIdx.x;      /* heavy tiles first */
    const int bh = blockIdx.y;
    const int b  = bh >> 4;
    const int h  = bh & 15;
    const int qbase = qt * 128;

    const __half* qp = q + ((size_t)b * CS + qbase) * CD + h * 64;
    const __half* kp = k + ((size_t)b * CS) * CD + h * 64;
    const __half* vp = v + ((size_t)b * CS) * CD + h * 64;

    const int srow = tid >> 2;           /* 0..63 */
    const int scol = (tid & 3) * 16;     /* 0,16,32,48 */

#define F_ISSUE(kt, buf) do {                                                \
        const __half* ksrc = kp + (size_t)((kt) * 64 + srow) * CD + scol;    \
        unsigned dk = sptr(KsB + (buf) * 64 * FQH + srow * FQH + scol);      \
        cpa16(dk,      ksrc);                                                \
        cpa16(dk + 16, ksrc + 8);                                            \
        const __half* vsrc = vp + (size_t)((kt) * 64 + srow) * CD + scol;    \
        unsigned dv = sptr(VsB + (buf) * 64 * FQH + srow * FQH + scol);      \
        cpa16(dv,      vsrc);                                                \
        cpa16(dv + 16, vsrc + 8);                                            \
        asm volatile("cp.async.commit_group;");                              \
    } while (0)

    F_ISSUE(0, 0);
    {
        int r  = tid >> 1;
        int c0 = (tid & 1) * 32;
        const __half* src = qp + (size_t)r * CD + c0;
#pragma unroll
        for (int j = 0; j < 4; j++)
            *(uint4*)&Qs[r * FQH + c0 + j * 8] = *(const uint4*)(src + j * 8);
    }
    __syncthreads();

    unsigned qf[4][4];
#pragma unroll
    for (int ks = 0; ks < 4; ks++)
        ldsm4(qf[ks][0], qf[ks][1], qf[ks][2], qf[ks][3],
              sptr(&Qs[(warp * 16 + l15) * FQH + ks * 16 + lk8]));

    float o[8][4];
#pragma unroll
    for (int dt = 0; dt < 8; dt++)
#pragma unroll
        for (int i = 0; i < 4; i++) o[dt][i] = 0.f;
    float mrow0 = -1e30f, mrow1 = -1e30f;
    float lrow0 = 0.f,    lrow1 = 0.f;

    const int qrow0 = qbase + warp * 16;
    const int nkt = (qbase >> 6) + 2;
    const float SC = 0.18033688f;   /* (1/8) * log2(e) */

    int buf = 0;
    for (int kt = 0; kt < nkt; kt++) {
        asm volatile("cp.async.wait_group 0;");
        __syncthreads();   /* K/V[buf] ready; all warps done with buf^1 */
        if (kt + 1 < nkt) F_ISSUE(kt + 1, buf ^ 1);

        if (kt * 64 <= qrow0 + 15) {
            const __half* Ks = KsB + buf * 64 * FQH;
            const __half* Vs = VsB + buf * 64 * FQH;

            float s[8][4];
#pragma unroll
            for (int nt = 0; nt < 8; nt++)
#pragma unroll
                for (int i = 0; i < 4; i++) s[nt][i] = 0.f;
#pragma unroll
            for (int ks = 0; ks < 4; ks++) {
#pragma unroll
                for (int nt2 = 0; nt2 < 4; nt2++) {
                    unsigned b0, b1, b2, b3;
                    ldsm4(b0, b1, b2, b3,
                          sptr(&Ks[(nt2 * 16 + (lane & 7) + lk8) * FQH
                                   + ks * 16 + (lane & 8)]));
                    mma16816(s[2 * nt2],     qf[ks], b0, b1);
                    mma16816(s[2 * nt2 + 1], qf[ks], b2, b3);
                }
            }

            const bool dg = (kt * 64 + 63 > qrow0);
            const int r0r = qrow0 + gr, r1r = qrow0 + gr + 8;
#pragma unroll
            for (int nt = 0; nt < 8; nt++) {
                int col = kt * 64 + nt * 8 + 2 * tg;
                if (dg) {
                    s[nt][0] = (col     > r0r) ? -1e30f : s[nt][0] * SC;
                    s[nt][1] = (col + 1 > r0r) ? -1e30f : s[nt][1] * SC;
                    s[nt][2] = (col     > r1r) ? -1e30f : s[nt][2] * SC;
                    s[nt][3] = (col + 1 > r1r) ? -1e30f : s[nt][3] * SC;
                } else {
                    s[nt][0] *= SC; s[nt][1] *= SC;
                    s[nt][2] *= SC; s[nt][3] *= SC;
                }
            }

            float mx0 = -1e30f, mx1 = -1e30f;
#pragma unroll
            for (int nt = 0; nt < 8; nt++) {
                mx0 = fmaxf(mx0, fmaxf(s[nt][0], s[nt][1]));
                mx1 = fmaxf(mx1, fmaxf(s[nt][2], s[nt][3]));
            }
            mx0 = fmaxf(mx0, __shfl_xor_sync(0xffffffffu, mx0, 1));
            mx0 = fmaxf(mx0, __shfl_xor_sync(0xffffffffu, mx0, 2));
            mx1 = fmaxf(mx1, __shfl_xor_sync(0xffffffffu, mx1, 1));
            mx1 = fmaxf(mx1, __shfl_xor_sync(0xffffffffu, mx1, 2));
            float mn0 = fmaxf(mrow0, mx0), mn1 = fmaxf(mrow1, mx1);
            float rs0 = ex2(mrow0 - mn0), rs1 = ex2(mrow1 - mn1);
            mrow0 = mn0; mrow1 = mn1;
            float ls0 = 0.f, ls1 = 0.f;
#pragma unroll
            for (int nt = 0; nt < 8; nt++) {
                s[nt][0] = ex2(s[nt][0] - mn0); ls0 += s[nt][0];
                s[nt][1] = ex2(s[nt][1] - mn0); ls0 += s[nt][1];
                s[nt][2] = ex2(s[nt][2] - mn1); ls1 += s[nt][2];
                s[nt][3] = ex2(s[nt][3] - mn1); ls1 += s[nt][3];
            }
            ls0 += __shfl_xor_sync(0xffffffffu, ls0, 1);
            ls0 += __shfl_xor_sync(0xffffffffu, ls0, 2);
            ls1 += __shfl_xor_sync(0xffffffffu, ls1, 1);
            ls1 += __shfl_xor_sync(0xffffffffu, ls1, 2);
            lrow0 = lrow0 * rs0 + ls0;
            lrow1 = lrow1 * rs1 + ls1;

#pragma unroll
            for (int dt = 0; dt < 8; dt++) {
                o[dt][0] *= rs0; o[dt][1] *= rs0;
                o[dt][2] *= rs1; o[dt][3] *= rs1;
            }

            unsigned pf[4][4];
#pragma unroll
            for (int ks = 0; ks < 4; ks++) {
                pf[ks][0] = packh2(s[2 * ks][0],     s[2 * ks][1]);
                pf[ks][1] = packh2(s[2 * ks][2],     s[2 * ks][3]);
                pf[ks][2] = packh2(s[2 * ks + 1][0], s[2 * ks + 1][1]);
                pf[ks][3] = packh2(s[2 * ks + 1][2], s[2 * ks + 1][3]);
            }

#pragma unroll
            for (int ks = 0; ks < 4; ks++) {
#pragma unroll
                for (int dt2 = 0; dt2 < 4; dt2++) {
                    unsigned b0, b1, b2, b3;
                    ldsm4t(b0, b1, b2, b3,
                           sptr(&Vs[(ks * 16 + (lane & 7) + (lane & 8)) * FQH
                                    + dt2 * 16 + lk8]));
                    mma16816(o[2 * dt2],     pf[ks], b0, b1);
                    mma16816(o[2 * dt2 + 1], pf[ks], b2, b3);
                }
            }
        }
        buf ^= 1;
    }
#undef F_ISSUE

    float inv0 = 1.f / lrow0, inv1 = 1.f / lrow1;
    __half* op = ctx + ((size_t)b * CS + qrow0) * CD + h * 64;
#pragma unroll
    for (int dt = 0; dt < 8; dt++) {
        int col = dt * 8 + 2 * tg;
        *reinterpret_cast<unsigned*>(op + (size_t)gr * CD + col) =
            packh2(o[dt][0] * inv0, o[dt][1] * inv0);
        *reinterpret_cast<unsigned*>(op + (size_t)(gr + 8) * CD + col) =
            packh2(o[dt][2] * inv1, o[dt][3] * inv1);
    }
}

/* ------------------------------------------------------------------ */
extern "C" void kernel_launch(void* const* d_in, const int* in_sizes, int n_in,
                              void* d_out, int out_size)
{
    const float* Q  = (const float*)d_in[0];
    const float* KV = (const float*)d_in[1];
    /* d_in[2] = mask — causal, applied analytically */
    const float* Wq = (const float*)d_in[3];
    const float* bq = (const float*)d_in[4];
    const float* Wk = (const float*)d_in[5];
    const float* bk = (const float*)d_in[6];
    const float* Wv = (const float*)d_in[7];
    const float* bv = (const float*)d_in[8];
    const float* Wo = (const float*)d_in[9];
    const float* bo = (const float*)d_in[10];
    float* out = (float*)d_out;

    __half *hQ, *hKV, *hWq, *hWk, *hWv, *hWo, *hq, *hk, *hv, *hctx;
    cudaGetSymbolAddress((void**)&hQ,   g_hQ);
    cudaGetSymbolAddress((void**)&hKV,  g_hKV);
    cudaGetSymbolAddress((void**)&hWq,  g_hWq);
    cudaGetSymbolAddress((void**)&hWk,  g_hWk);
    cudaGetSymbolAddress((void**)&hWv,  g_hWv);
    cudaGetSymbolAddress((void**)&hWo,  g_hWo);
    cudaGetSymbolAddress((void**)&hq,   g_hq);
    cudaGetSymbolAddress((void**)&hk,   g_hk);
    cudaGetSymbolAddress((void**)&hv,   g_hv);
    cudaGetSymbolAddress((void**)&hctx, g_hctx);

    static bool attr_done = false;
    if (!attr_done) {
        cudaFuncSetAttribute(gemm_qkv_kernel,
                             cudaFuncAttributeMaxDynamicSharedMemorySize, GEMM_SMEM);
        cudaFuncSetAttribute(gemm_wo_kernel,
                             cudaFuncAttributeMaxDynamicSharedMemorySize, GEMM_SMEM);
        cudaFuncSetAttribute(flash_h_kernel,
                             cudaFuncAttributeMaxDynamicSharedMemorySize, FLASH_SMEM);
        attr_done = true;
    }

    const int NTOK4 = MTOK * CD / 4;   /* 2M float4 */
    const int NW4   = CD * CD / 4;     /* 256K float4 */
    f2h2_kernel<<<dim3(1184, 2), 256>>>((const float4*)Q, (const float4*)KV,
                                        (uint2*)hQ, (uint2*)hKV, NTOK4);
    f2h4_kernel<<<dim3(296, 4), 256>>>(
        (const float4*)Wq, (const float4*)Wk, (const float4*)Wv, (const float4*)Wo,
        (uint2*)hWq, (uint2*)hWk, (uint2*)hWv, (uint2*)hWo, NW4);

    /* fused q/k/v projections: one launch, better wave packing + A reuse */
    dim3 gqkv(GN / 128, GM / 128, 3);   /* (8, 64, 3) */
    gemm_qkv_kernel<<<gqkv, 256, GEMM_SMEM>>>(hQ, hKV, hWq, hWk, hWv,
                                              bq, bk, bv, hq, hk, hv);

    dim3 gf(16, CB * CH);          /* (16, 64) */
    flash_h_kernel<<<gf, 256, FLASH_SMEM>>>(hq, hk, hv, hctx);

    dim3 gg(GN / 128, GM / 128);   /* (8, 64) */
    gemm_wo_kernel<<<gg, 256, GEMM_SMEM>>>(hctx, hWo, bo, out);
}